// round 1
// baseline (speedup 1.0000x reference)
#include <cuda_runtime.h>
#include <math.h>

#define NNODES 100000
#define NEDGES 1600000
#define NEG 0.2f

// ---------------- scratch (device globals; no allocation allowed) ----------
__device__ float g_h1[NNODES * 128];   // layer1 projected features [N,4,32]
__device__ float g_el1[NNODES * 4];
__device__ float g_er1[NNODES * 4];
__device__ float g_x2[NNODES * 128];   // layer1 output after elu (input to layer2)
__device__ float g_h2[NNODES * 32];    // layer2 projected features
__device__ float g_el2[NNODES];
__device__ float g_er2[NNODES];
__device__ int   g_deg[NNODES];
__device__ int   g_rowptr[NNODES + 1];
__device__ int   g_cursor[NNODES];
__device__ int   g_csrc[NEDGES];
__device__ int   g_bsums[128];
__device__ int   g_boff[128];

__device__ __forceinline__ void fma4(float4& a, float s, float4 b) {
    a.x = fmaf(s, b.x, a.x);
    a.y = fmaf(s, b.y, a.y);
    a.z = fmaf(s, b.z, a.z);
    a.w = fmaf(s, b.w, a.w);
}
__device__ __forceinline__ float dot4(float4 a, float4 b) {
    return a.x * b.x + a.y * b.y + a.z * b.z + a.w * b.w;
}

// ---------------- GEMM1: h1 = x @ W1, fused el/er ---------------------------
// block = 128 threads, 16 nodes per block.
// warp w handles nodes nb + 4w .. +3 ; lane l owns columns 4l..4l+3.
__global__ __launch_bounds__(128) void gemm1_kernel(
    const float* __restrict__ x, const float* __restrict__ W,
    const float* __restrict__ al, const float* __restrict__ ar) {
    __shared__ float4 sX[16 * 32];
    int tid = threadIdx.x;
    int nb = blockIdx.x * 16;
    for (int i = tid; i < 16 * 32; i += 128) {
        int nn = nb + (i >> 5);
        sX[i] = (nn < NNODES) ? ((const float4*)x)[(size_t)nn * 32 + (i & 31)]
                              : make_float4(0.f, 0.f, 0.f, 0.f);
    }
    __syncthreads();
    int l = tid & 31, w = tid >> 5;
    int h = l >> 3, o = l & 7;
    float4 alv = ((const float4*)al)[h * 8 + o];
    float4 arv = ((const float4*)ar)[h * 8 + o];
    float4 acc[4];
#pragma unroll
    for (int i = 0; i < 4; i++) acc[i] = make_float4(0.f, 0.f, 0.f, 0.f);
    const float4* xw = sX + (w * 4) * 32;
    const float4* W4 = (const float4*)W;
#pragma unroll 8
    for (int k4 = 0; k4 < 32; ++k4) {
        float4 w0 = __ldg(&W4[(4 * k4 + 0) * 32 + l]);
        float4 w1 = __ldg(&W4[(4 * k4 + 1) * 32 + l]);
        float4 w2 = __ldg(&W4[(4 * k4 + 2) * 32 + l]);
        float4 w3 = __ldg(&W4[(4 * k4 + 3) * 32 + l]);
#pragma unroll
        for (int i = 0; i < 4; i++) {
            float4 xv = xw[i * 32 + k4];
            fma4(acc[i], xv.x, w0);
            fma4(acc[i], xv.y, w1);
            fma4(acc[i], xv.z, w2);
            fma4(acc[i], xv.w, w3);
        }
    }
#pragma unroll
    for (int i = 0; i < 4; i++) {
        int n = nb + w * 4 + i;
        float4 a = acc[i];
        float pel = dot4(a, alv);
        float per = dot4(a, arv);
#pragma unroll
        for (int d = 4; d >= 1; d >>= 1) {
            pel += __shfl_down_sync(0xffffffffu, pel, d);
            per += __shfl_down_sync(0xffffffffu, per, d);
        }
        if (n < NNODES) {
            ((float4*)g_h1)[(size_t)n * 32 + l] = a;
            if (o == 0) { g_el1[n * 4 + h] = pel; g_er1[n * 4 + h] = per; }
        }
    }
}

// ---------------- GEMM2: h2 = x2 @ W2, fused el2/er2 ------------------------
// block = 128 threads, 64 nodes per block. lane: o=l&7 -> col group, g=l>>3 ->
// node subgroup; each thread does 4 nodes x 4 cols.
__global__ __launch_bounds__(128) void gemm2_kernel(
    const float* __restrict__ W, const float* __restrict__ al,
    const float* __restrict__ ar) {
    __shared__ float4 sX[64 * 32];  // 32 KB
    int tid = threadIdx.x;
    int nb = blockIdx.x * 64;
    for (int i = tid; i < 64 * 32; i += 128) {
        int nn = nb + (i >> 5);
        sX[i] = (nn < NNODES) ? ((const float4*)g_x2)[(size_t)nn * 32 + (i & 31)]
                              : make_float4(0.f, 0.f, 0.f, 0.f);
    }
    __syncthreads();
    int l = tid & 31, w = tid >> 5;
    int o = l & 7, g = l >> 3;
    float4 alv = ((const float4*)al)[o];
    float4 arv = ((const float4*)ar)[o];
    float4 acc[4];
#pragma unroll
    for (int i = 0; i < 4; i++) acc[i] = make_float4(0.f, 0.f, 0.f, 0.f);
    const float4* xw = sX + (w * 16 + g * 4) * 32;
    const float4* W4 = (const float4*)W;
#pragma unroll 8
    for (int k4 = 0; k4 < 32; ++k4) {
        float4 w0 = __ldg(&W4[(4 * k4 + 0) * 8 + o]);
        float4 w1 = __ldg(&W4[(4 * k4 + 1) * 8 + o]);
        float4 w2 = __ldg(&W4[(4 * k4 + 2) * 8 + o]);
        float4 w3 = __ldg(&W4[(4 * k4 + 3) * 8 + o]);
#pragma unroll
        for (int i = 0; i < 4; i++) {
            float4 xv = xw[i * 32 + k4];
            fma4(acc[i], xv.x, w0);
            fma4(acc[i], xv.y, w1);
            fma4(acc[i], xv.z, w2);
            fma4(acc[i], xv.w, w3);
        }
    }
#pragma unroll
    for (int i = 0; i < 4; i++) {
        int n = nb + w * 16 + g * 4 + i;
        float4 a = acc[i];
        float pel = dot4(a, alv);
        float per = dot4(a, arv);
#pragma unroll
        for (int d = 4; d >= 1; d >>= 1) {
            pel += __shfl_down_sync(0xffffffffu, pel, d);
            per += __shfl_down_sync(0xffffffffu, per, d);
        }
        if (n < NNODES) {
            ((float4*)g_h2)[(size_t)n * 8 + o] = a;
            if (o == 0) { g_el2[n] = pel; g_er2[n] = per; }
        }
    }
}

// ---------------- CSR build -------------------------------------------------
__global__ void zero_deg_kernel() {
    int i = blockIdx.x * blockDim.x + threadIdx.x;
    if (i < NNODES) g_deg[i] = 0;
}
__global__ void count_kernel(const int* __restrict__ dst) {
    int i = blockIdx.x * blockDim.x + threadIdx.x;
    if (i < NEDGES) atomicAdd(&g_deg[dst[i]], 1);
}
__global__ void scan1_kernel() {
    __shared__ int s[1024];
    int i = blockIdx.x * 1024 + threadIdx.x;
    int v = (i < NNODES) ? g_deg[i] : 0;
    s[threadIdx.x] = v;
    __syncthreads();
    for (int off = 1; off < 1024; off <<= 1) {
        int t = (threadIdx.x >= off) ? s[threadIdx.x - off] : 0;
        __syncthreads();
        s[threadIdx.x] += t;
        __syncthreads();
    }
    if (i < NNODES) g_rowptr[i + 1] = s[threadIdx.x];
    if (threadIdx.x == 1023) g_bsums[blockIdx.x] = s[1023];
}
__global__ void scan2_kernel(int nblk) {
    __shared__ int s[128];
    int v = (threadIdx.x < nblk) ? g_bsums[threadIdx.x] : 0;
    s[threadIdx.x] = v;
    __syncthreads();
    for (int off = 1; off < 128; off <<= 1) {
        int t = (threadIdx.x >= off) ? s[threadIdx.x - off] : 0;
        __syncthreads();
        s[threadIdx.x] += t;
        __syncthreads();
    }
    g_boff[threadIdx.x] = s[threadIdx.x] - v;  // exclusive prefix of block sums
}
__global__ void scan3_kernel() {
    int i = blockIdx.x * 1024 + threadIdx.x;
    if (i < NNODES) g_rowptr[i + 1] += g_boff[blockIdx.x];
    if (i == 0) g_rowptr[0] = 0;
}
__global__ void cursor_kernel() {
    int i = blockIdx.x * blockDim.x + threadIdx.x;
    if (i < NNODES) g_cursor[i] = g_rowptr[i];
}
__global__ void fill_kernel(const int* __restrict__ src, const int* __restrict__ dst) {
    int i = blockIdx.x * blockDim.x + threadIdx.x;
    if (i < NEDGES) {
        int d = dst[i];
        int p = atomicAdd(&g_cursor[d], 1);
        g_csrc[p] = src[i];
    }
}

// ---------------- AGG layer1: warp per dst node, 2-pass softmax -------------
// lane l: head h=l>>3, dims 4*(l&7)..+3  -> feature column 4l..4l+3
__global__ __launch_bounds__(256) void agg1_kernel(const float* __restrict__ b1) {
    int gwarp = (blockIdx.x * 256 + threadIdx.x) >> 5;
    if (gwarp >= NNODES) return;
    int l = threadIdx.x & 31;
    int n = gwarp;
    int h = l >> 3;
    int s0 = g_rowptr[n], s1 = g_rowptr[n + 1];
    float4 bv = ((const float4*)b1)[l];
    float4 res;
    if (s0 == s1) {
        res = bv;
    } else {
        float ern = g_er1[n * 4 + h];
        float mx = -INFINITY;
        for (int j = s0; j < s1; ++j) {
            int s = g_csrc[j];
            float e = g_el1[s * 4 + h] + ern;
            e = (e > 0.f) ? e : NEG * e;
            mx = fmaxf(mx, e);
        }
        float sm = 0.f;
        float4 acc = make_float4(0.f, 0.f, 0.f, 0.f);
        for (int j = s0; j < s1; ++j) {
            int s = g_csrc[j];
            float e = g_el1[s * 4 + h] + ern;
            e = (e > 0.f) ? e : NEG * e;
            float wg = __expf(e - mx);
            sm += wg;
            float4 f = ((const float4*)g_h1)[(size_t)s * 32 + l];
            fma4(acc, wg, f);
        }
        float inv = 1.f / sm;
        res = make_float4(fmaf(acc.x, inv, bv.x), fmaf(acc.y, inv, bv.y),
                          fmaf(acc.z, inv, bv.z), fmaf(acc.w, inv, bv.w));
    }
    // elu
    res.x = res.x > 0.f ? res.x : expm1f(res.x);
    res.y = res.y > 0.f ? res.y : expm1f(res.y);
    res.z = res.z > 0.f ? res.z : expm1f(res.z);
    res.w = res.w > 0.f ? res.w : expm1f(res.w);
    ((float4*)g_x2)[(size_t)n * 32 + l] = res;
}

// ---------------- AGG layer2: warp per dst node, H=1, D=32 ------------------
__global__ __launch_bounds__(256) void agg2_kernel(const float* __restrict__ b2,
                                                   float* __restrict__ out) {
    int gwarp = (blockIdx.x * 256 + threadIdx.x) >> 5;
    if (gwarp >= NNODES) return;
    int l = threadIdx.x & 31;
    int n = gwarp;
    int s0 = g_rowptr[n], s1 = g_rowptr[n + 1];
    float bv = b2[l];
    float val;
    if (s0 == s1) {
        val = bv;
    } else {
        float ern = g_er2[n];
        float mx = -INFINITY;
        for (int j = s0; j < s1; ++j) {
            float e = g_el2[g_csrc[j]] + ern;
            e = (e > 0.f) ? e : NEG * e;
            mx = fmaxf(mx, e);
        }
        float sm = 0.f, acc = 0.f;
        for (int j = s0; j < s1; ++j) {
            int s = g_csrc[j];
            float e = g_el2[s] + ern;
            e = (e > 0.f) ? e : NEG * e;
            float wg = __expf(e - mx);
            sm += wg;
            acc = fmaf(wg, __ldg(&g_h2[(size_t)s * 32 + l]), acc);
        }
        val = acc / sm + bv;
    }
    out[(size_t)n * 32 + l] = val;
}

// ---------------- launch ----------------------------------------------------
extern "C" void kernel_launch(void* const* d_in, const int* in_sizes, int n_in,
                              void* d_out, int out_size) {
    const float* x   = (const float*)d_in[0];
    const int*   src = (const int*)d_in[1];
    const int*   dst = (const int*)d_in[2];
    const float* W1  = (const float*)d_in[3];
    const float* al1 = (const float*)d_in[4];
    const float* ar1 = (const float*)d_in[5];
    const float* b1  = (const float*)d_in[6];
    const float* W2  = (const float*)d_in[7];
    const float* al2 = (const float*)d_in[8];
    const float* ar2 = (const float*)d_in[9];
    const float* b2  = (const float*)d_in[10];
    float* out = (float*)d_out;

    const int nscan = (NNODES + 1023) / 1024;

    gemm1_kernel<<<(NNODES + 15) / 16, 128>>>(x, W1, al1, ar1);

    zero_deg_kernel<<<(NNODES + 255) / 256, 256>>>();
    count_kernel<<<(NEDGES + 255) / 256, 256>>>(dst);
    scan1_kernel<<<nscan, 1024>>>();
    scan2_kernel<<<1, 128>>>(nscan);
    scan3_kernel<<<nscan, 1024>>>();
    cursor_kernel<<<(NNODES + 255) / 256, 256>>>();
    fill_kernel<<<(NEDGES + 255) / 256, 256>>>(src, dst);

    agg1_kernel<<<(NNODES * 32 + 255) / 256, 256>>>(b1);
    gemm2_kernel<<<(NNODES + 63) / 64, 128>>>(W2, al2, ar2);
    agg2_kernel<<<(NNODES * 32 + 255) / 256, 256>>>(b2, out);
}

// round 2
// speedup vs baseline: 1.1213x; 1.1213x over previous
#include <cuda_runtime.h>
#include <cuda_fp16.h>
#include <math.h>

#define NNODES 100000
#define NEDGES 1600000
#define NEG 0.2f

// ---------------- scratch (device globals; no allocation allowed) ----------
__device__ __half g_h1[NNODES * 128];   // layer1 projected features, fp16 [N,4,32]
__device__ float  g_el1[NNODES * 4];
__device__ float  g_er1[NNODES * 4];
__device__ float  g_x2[NNODES * 128];   // layer1 output after elu (fp32, gemm2 input)
__device__ __half g_h2[NNODES * 32];    // layer2 projected features, fp16
__device__ float  g_el2[NNODES];
__device__ float  g_er2[NNODES];
__device__ int    g_deg[NNODES];
__device__ int    g_rowptr[NNODES + 1];
__device__ int    g_cursor[NNODES];
__device__ int    g_csrc[NEDGES];
__device__ int    g_bsums[128];
__device__ int    g_boff[128];

__device__ __forceinline__ void fma4(float4& a, float s, float4 b) {
    a.x = fmaf(s, b.x, a.x);
    a.y = fmaf(s, b.y, a.y);
    a.z = fmaf(s, b.z, a.z);
    a.w = fmaf(s, b.w, a.w);
}
__device__ __forceinline__ float dot4(float4 a, float4 b) {
    return a.x * b.x + a.y * b.y + a.z * b.z + a.w * b.w;
}
__device__ __forceinline__ uint2 pack_half4(float4 a) {
    __half2 p0 = __floats2half2_rn(a.x, a.y);
    __half2 p1 = __floats2half2_rn(a.z, a.w);
    uint2 u;
    u.x = *(unsigned*)&p0;
    u.y = *(unsigned*)&p1;
    return u;
}

// ---------------- GEMM1: h1 = x @ W1 (fp16 out), fused el/er ----------------
// block = 128 threads, 16 nodes per block; lane l owns columns 4l..4l+3.
__global__ __launch_bounds__(128) void gemm1_kernel(
    const float* __restrict__ x, const float* __restrict__ W,
    const float* __restrict__ al, const float* __restrict__ ar) {
    __shared__ float4 sX[16 * 32];
    int tid = threadIdx.x;
    int nb = blockIdx.x * 16;
    for (int i = tid; i < 16 * 32; i += 128) {
        int nn = nb + (i >> 5);
        sX[i] = (nn < NNODES) ? ((const float4*)x)[(size_t)nn * 32 + (i & 31)]
                              : make_float4(0.f, 0.f, 0.f, 0.f);
    }
    __syncthreads();
    int l = tid & 31, w = tid >> 5;
    int h = l >> 3, o = l & 7;
    float4 alv = ((const float4*)al)[h * 8 + o];
    float4 arv = ((const float4*)ar)[h * 8 + o];
    float4 acc[4];
#pragma unroll
    for (int i = 0; i < 4; i++) acc[i] = make_float4(0.f, 0.f, 0.f, 0.f);
    const float4* xw = sX + (w * 4) * 32;
    const float4* W4 = (const float4*)W;
#pragma unroll 8
    for (int k4 = 0; k4 < 32; ++k4) {
        float4 w0 = __ldg(&W4[(4 * k4 + 0) * 32 + l]);
        float4 w1 = __ldg(&W4[(4 * k4 + 1) * 32 + l]);
        float4 w2 = __ldg(&W4[(4 * k4 + 2) * 32 + l]);
        float4 w3 = __ldg(&W4[(4 * k4 + 3) * 32 + l]);
#pragma unroll
        for (int i = 0; i < 4; i++) {
            float4 xv = xw[i * 32 + k4];
            fma4(acc[i], xv.x, w0);
            fma4(acc[i], xv.y, w1);
            fma4(acc[i], xv.z, w2);
            fma4(acc[i], xv.w, w3);
        }
    }
#pragma unroll
    for (int i = 0; i < 4; i++) {
        int n = nb + w * 4 + i;
        float4 a = acc[i];
        float pel = dot4(a, alv);
        float per = dot4(a, arv);
#pragma unroll
        for (int d = 4; d >= 1; d >>= 1) {
            pel += __shfl_down_sync(0xffffffffu, pel, d);
            per += __shfl_down_sync(0xffffffffu, per, d);
        }
        if (n < NNODES) {
            ((uint2*)g_h1)[(size_t)n * 32 + l] = pack_half4(a);
            if (o == 0) { g_el1[n * 4 + h] = pel; g_er1[n * 4 + h] = per; }
        }
    }
}

// ---------------- GEMM2: h2 = x2 @ W2 (fp16 out), fused el2/er2 -------------
__global__ __launch_bounds__(128) void gemm2_kernel(
    const float* __restrict__ W, const float* __restrict__ al,
    const float* __restrict__ ar) {
    __shared__ float4 sX[64 * 32];  // 32 KB
    int tid = threadIdx.x;
    int nb = blockIdx.x * 64;
    for (int i = tid; i < 64 * 32; i += 128) {
        int nn = nb + (i >> 5);
        sX[i] = (nn < NNODES) ? ((const float4*)g_x2)[(size_t)nn * 32 + (i & 31)]
                              : make_float4(0.f, 0.f, 0.f, 0.f);
    }
    __syncthreads();
    int l = tid & 31, w = tid >> 5;
    int o = l & 7, g = l >> 3;
    float4 alv = ((const float4*)al)[o];
    float4 arv = ((const float4*)ar)[o];
    float4 acc[4];
#pragma unroll
    for (int i = 0; i < 4; i++) acc[i] = make_float4(0.f, 0.f, 0.f, 0.f);
    const float4* xw = sX + (w * 16 + g * 4) * 32;
    const float4* W4 = (const float4*)W;
#pragma unroll 8
    for (int k4 = 0; k4 < 32; ++k4) {
        float4 w0 = __ldg(&W4[(4 * k4 + 0) * 8 + o]);
        float4 w1 = __ldg(&W4[(4 * k4 + 1) * 8 + o]);
        float4 w2 = __ldg(&W4[(4 * k4 + 2) * 8 + o]);
        float4 w3 = __ldg(&W4[(4 * k4 + 3) * 8 + o]);
#pragma unroll
        for (int i = 0; i < 4; i++) {
            float4 xv = xw[i * 32 + k4];
            fma4(acc[i], xv.x, w0);
            fma4(acc[i], xv.y, w1);
            fma4(acc[i], xv.z, w2);
            fma4(acc[i], xv.w, w3);
        }
    }
#pragma unroll
    for (int i = 0; i < 4; i++) {
        int n = nb + w * 16 + g * 4 + i;
        float4 a = acc[i];
        float pel = dot4(a, alv);
        float per = dot4(a, arv);
#pragma unroll
        for (int d = 4; d >= 1; d >>= 1) {
            pel += __shfl_down_sync(0xffffffffu, pel, d);
            per += __shfl_down_sync(0xffffffffu, per, d);
        }
        if (n < NNODES) {
            ((uint2*)g_h2)[(size_t)n * 8 + o] = pack_half4(a);
            if (o == 0) { g_el2[n] = pel; g_er2[n] = per; }
        }
    }
}

// ---------------- CSR build -------------------------------------------------
__global__ void zero_deg_kernel() {
    int i = blockIdx.x * blockDim.x + threadIdx.x;
    if (i < NNODES) g_deg[i] = 0;
}
__global__ void count_kernel(const int* __restrict__ dst) {
    int i = blockIdx.x * blockDim.x + threadIdx.x;
    if (i < NEDGES) atomicAdd(&g_deg[dst[i]], 1);
}
__global__ void scan1_kernel() {
    __shared__ int s[1024];
    int i = blockIdx.x * 1024 + threadIdx.x;
    int v = (i < NNODES) ? g_deg[i] : 0;
    s[threadIdx.x] = v;
    __syncthreads();
    for (int off = 1; off < 1024; off <<= 1) {
        int t = (threadIdx.x >= off) ? s[threadIdx.x - off] : 0;
        __syncthreads();
        s[threadIdx.x] += t;
        __syncthreads();
    }
    if (i < NNODES) g_rowptr[i + 1] = s[threadIdx.x];
    if (threadIdx.x == 1023) g_bsums[blockIdx.x] = s[1023];
}
__global__ void scan2_kernel(int nblk) {
    __shared__ int s[128];
    int v = (threadIdx.x < nblk) ? g_bsums[threadIdx.x] : 0;
    s[threadIdx.x] = v;
    __syncthreads();
    for (int off = 1; off < 128; off <<= 1) {
        int t = (threadIdx.x >= off) ? s[threadIdx.x - off] : 0;
        __syncthreads();
        s[threadIdx.x] += t;
        __syncthreads();
    }
    g_boff[threadIdx.x] = s[threadIdx.x] - v;  // exclusive prefix of block sums
}
__global__ void scan3_kernel() {    // finalize rowptr AND init cursor
    int i = blockIdx.x * 1024 + threadIdx.x;
    if (i < NNODES) {
        int v = g_rowptr[i + 1] + g_boff[blockIdx.x];
        g_rowptr[i + 1] = v;
        if (i + 1 < NNODES) g_cursor[i + 1] = v;
    }
    if (i == 0) { g_rowptr[0] = 0; g_cursor[0] = 0; }
}
__global__ void fill_kernel(const int* __restrict__ src, const int* __restrict__ dst) {
    int i = blockIdx.x * blockDim.x + threadIdx.x;
    if (i < NEDGES) {
        int d = dst[i];
        int p = atomicAdd(&g_cursor[d], 1);
        g_csrc[p] = src[i];
    }
}

// ---------------- AGG layer1: warp per dst node, 1-pass softmax -------------
// lane l: head h=l>>3, feature columns 4l..4l+3 (fp16 gather)
__global__ __launch_bounds__(256) void agg1_kernel(const float* __restrict__ b1) {
    int n = (blockIdx.x * 256 + threadIdx.x) >> 5;
    if (n >= NNODES) return;
    int l = threadIdx.x & 31;
    int h = l >> 3;
    int s0 = g_rowptr[n], s1 = g_rowptr[n + 1];
    float4 bv = ((const float4*)b1)[l];
    float4 res = bv;
    if (s1 > s0) {
        float ern = g_er1[n * 4 + h];
        float sm = 0.f;
        float4 acc = make_float4(0.f, 0.f, 0.f, 0.f);
        int s = g_csrc[s0];
        for (int j = s0; j < s1; ++j) {
            int snext = (j + 1 < s1) ? g_csrc[j + 1] : 0;
            float e = g_el1[s * 4 + h] + ern;
            e = (e > 0.f) ? e : NEG * e;
            float wg = __expf(fminf(e, 60.f));
            uint2 p = ((const uint2*)g_h1)[(size_t)s * 32 + l];
            float2 f01 = __half22float2(*(__half2*)&p.x);
            float2 f23 = __half22float2(*(__half2*)&p.y);
            sm += wg;
            acc.x = fmaf(wg, f01.x, acc.x);
            acc.y = fmaf(wg, f01.y, acc.y);
            acc.z = fmaf(wg, f23.x, acc.z);
            acc.w = fmaf(wg, f23.y, acc.w);
            s = snext;
        }
        float inv = 1.f / sm;
        res = make_float4(fmaf(acc.x, inv, bv.x), fmaf(acc.y, inv, bv.y),
                          fmaf(acc.z, inv, bv.z), fmaf(acc.w, inv, bv.w));
    }
    // elu
    res.x = res.x > 0.f ? res.x : expm1f(res.x);
    res.y = res.y > 0.f ? res.y : expm1f(res.y);
    res.z = res.z > 0.f ? res.z : expm1f(res.z);
    res.w = res.w > 0.f ? res.w : expm1f(res.w);
    ((float4*)g_x2)[(size_t)n * 32 + l] = res;
}

// ---------------- AGG layer2: warp per dst node, H=1, D=32, 1-pass ----------
__global__ __launch_bounds__(256) void agg2_kernel(const float* __restrict__ b2,
                                                   float* __restrict__ out) {
    int n = (blockIdx.x * 256 + threadIdx.x) >> 5;
    if (n >= NNODES) return;
    int l = threadIdx.x & 31;
    int s0 = g_rowptr[n], s1 = g_rowptr[n + 1];
    float bv = b2[l];
    float val = bv;
    if (s1 > s0) {
        float ern = g_er2[n];
        float sm = 0.f, acc = 0.f;
        int s = g_csrc[s0];
        for (int j = s0; j < s1; ++j) {
            int snext = (j + 1 < s1) ? g_csrc[j + 1] : 0;
            float e = g_el2[s] + ern;
            e = (e > 0.f) ? e : NEG * e;
            float wg = __expf(fminf(e, 60.f));
            float f = __half2float(g_h2[(size_t)s * 32 + l]);
            sm += wg;
            acc = fmaf(wg, f, acc);
            s = snext;
        }
        val = acc / sm + bv;
    }
    out[(size_t)n * 32 + l] = val;
}

// ---------------- launch ----------------------------------------------------
extern "C" void kernel_launch(void* const* d_in, const int* in_sizes, int n_in,
                              void* d_out, int out_size) {
    const float* x   = (const float*)d_in[0];
    const int*   src = (const int*)d_in[1];
    const int*   dst = (const int*)d_in[2];
    const float* W1  = (const float*)d_in[3];
    const float* al1 = (const float*)d_in[4];
    const float* ar1 = (const float*)d_in[5];
    const float* b1  = (const float*)d_in[6];
    const float* W2  = (const float*)d_in[7];
    const float* al2 = (const float*)d_in[8];
    const float* ar2 = (const float*)d_in[9];
    const float* b2  = (const float*)d_in[10];
    float* out = (float*)d_out;

    const int nscan = (NNODES + 1023) / 1024;

    gemm1_kernel<<<(NNODES + 15) / 16, 128>>>(x, W1, al1, ar1);

    zero_deg_kernel<<<(NNODES + 255) / 256, 256>>>();
    count_kernel<<<(NEDGES + 255) / 256, 256>>>(dst);
    scan1_kernel<<<nscan, 1024>>>();
    scan2_kernel<<<1, 128>>>(nscan);
    scan3_kernel<<<nscan, 1024>>>();
    fill_kernel<<<(NEDGES + 255) / 256, 256>>>(src, dst);

    agg1_kernel<<<(NNODES * 32 + 255) / 256, 256>>>(b1);
    gemm2_kernel<<<(NNODES + 63) / 64, 128>>>(W2, al2, ar2);
    agg2_kernel<<<(NNODES * 32 + 255) / 256, 256>>>(b2, out);
}

// round 3
// speedup vs baseline: 1.2174x; 1.0857x over previous
#include <cuda_runtime.h>
#include <cuda_fp16.h>
#include <math.h>

#define NNODES 100000
#define NEDGES 1600000
#define NEG 0.2f

// ---------------- scratch (device globals; no allocation allowed) ----------
__device__ __half g_h1[NNODES * 128];   // layer1 projected features, fp16 [N,4,32]
__device__ float  g_el1[NNODES * 4];
__device__ float  g_er1[NNODES * 4];
__device__ float  g_x2[NNODES * 128];   // layer1 output after elu (fp32, gemm2 input)
__device__ __half g_h2[NNODES * 32];    // layer2 projected features, fp16
__device__ float  g_el2[NNODES];
__device__ float  g_er2[NNODES];
__device__ int    g_deg[NNODES];
__device__ int    g_rowptr[NNODES + 1];
__device__ int    g_cursor[NNODES];
__device__ int    g_csrc[NEDGES];
__device__ int    g_bsums[128];
__device__ int    g_boff[128];

__device__ __forceinline__ void fma4(float4& a, float s, float4 b) {
    a.x = fmaf(s, b.x, a.x);
    a.y = fmaf(s, b.y, a.y);
    a.z = fmaf(s, b.z, a.z);
    a.w = fmaf(s, b.w, a.w);
}
__device__ __forceinline__ float dot4(float4 a, float4 b) {
    return a.x * b.x + a.y * b.y + a.z * b.z + a.w * b.w;
}
__device__ __forceinline__ uint2 pack_half4(float4 a) {
    __half2 p0 = __floats2half2_rn(a.x, a.y);
    __half2 p1 = __floats2half2_rn(a.z, a.w);
    uint2 u;
    u.x = *(unsigned*)&p0;
    u.y = *(unsigned*)&p1;
    return u;
}

// ---------------- GEMM1 via HMMA: h1 = x @ W1 (fp16 out), fused el/er -------
// block = 128 threads (4 warps), 64 nodes/block; warp w -> rows w*16..w*16+15.
// mma.sync m16n8k16 row.col: A = x tile (fp16 smem), B = W^T (fp16 smem).
#define GM_ROWS 64
#define XS_STRIDE 136   // halves; 272 B rows -> conflict-free frag loads
#define WS_STRIDE 136
#define GEMM1_SMEM ((GM_ROWS * XS_STRIDE + 128 * WS_STRIDE) * 2)

__global__ __launch_bounds__(128) void gemm1_kernel(
    const float* __restrict__ x, const float* __restrict__ W,
    const float* __restrict__ al, const float* __restrict__ ar) {
    extern __shared__ __half smem_dyn[];
    __half* xs = smem_dyn;                        // [64][136]
    __half* ws = smem_dyn + GM_ROWS * XS_STRIDE;  // [128][136]  ws[n][k] = W[k][n]
    int tid = threadIdx.x;
    int nb = blockIdx.x * GM_ROWS;

    for (int i = tid; i < 128 * 128; i += 128) {
        int k = i >> 7, n = i & 127;
        ws[n * WS_STRIDE + k] = __float2half_rn(W[i]);
    }
    for (int i = tid; i < GM_ROWS * 128; i += 128) {
        int r = i >> 7, k = i & 127;
        int nn = nb + r;
        xs[r * XS_STRIDE + k] =
            (nn < NNODES) ? __float2half_rn(x[(size_t)nn * 128 + k]) : __half(0.f);
    }
    __syncthreads();

    int l = tid & 31, w = tid >> 5;
    int g4 = l >> 2, q = l & 3;
    float d[16][4];
#pragma unroll
    for (int nt = 0; nt < 16; ++nt)
#pragma unroll
        for (int c = 0; c < 4; ++c) d[nt][c] = 0.f;

    const __half* xw = xs + (w * 16) * XS_STRIDE;
#pragma unroll
    for (int ks = 0; ks < 8; ++ks) {
        int kb = ks * 16 + q * 2;
        unsigned a0 = *(const unsigned*)(xw + (g4    ) * XS_STRIDE + kb    );
        unsigned a1 = *(const unsigned*)(xw + (g4 + 8) * XS_STRIDE + kb    );
        unsigned a2 = *(const unsigned*)(xw + (g4    ) * XS_STRIDE + kb + 8);
        unsigned a3 = *(const unsigned*)(xw + (g4 + 8) * XS_STRIDE + kb + 8);
#pragma unroll
        for (int nt = 0; nt < 16; ++nt) {
            const __half* wb = ws + (nt * 8 + g4) * WS_STRIDE + kb;
            unsigned b0 = *(const unsigned*)(wb);
            unsigned b1 = *(const unsigned*)(wb + 8);
            asm volatile(
                "mma.sync.aligned.m16n8k16.row.col.f32.f16.f16.f32 "
                "{%0,%1,%2,%3}, {%4,%5,%6,%7}, {%8,%9}, {%0,%1,%2,%3};"
                : "+f"(d[nt][0]), "+f"(d[nt][1]), "+f"(d[nt][2]), "+f"(d[nt][3])
                : "r"(a0), "r"(a1), "r"(a2), "r"(a3), "r"(b0), "r"(b1));
        }
    }

    int r0 = nb + w * 16 + g4;  // global node rows for this thread
    int r1 = r0 + 8;
    // fused attention dots, per head (cols h*32..h*32+31 = n-tiles h*4..h*4+3)
#pragma unroll
    for (int h = 0; h < 4; ++h) {
        float pel0 = 0.f, per0 = 0.f, pel1 = 0.f, per1 = 0.f;
#pragma unroll
        for (int t = 0; t < 4; ++t) {
            int nt = h * 4 + t;
            int c0 = nt * 8 + q * 2;
            float alv0 = __ldg(&al[c0]), alv1 = __ldg(&al[c0 + 1]);
            float arv0 = __ldg(&ar[c0]), arv1 = __ldg(&ar[c0 + 1]);
            pel0 += d[nt][0] * alv0 + d[nt][1] * alv1;
            per0 += d[nt][0] * arv0 + d[nt][1] * arv1;
            pel1 += d[nt][2] * alv0 + d[nt][3] * alv1;
            per1 += d[nt][2] * arv0 + d[nt][3] * arv1;
        }
#pragma unroll
        for (int o = 1; o < 4; o <<= 1) {
            pel0 += __shfl_xor_sync(0xffffffffu, pel0, o);
            per0 += __shfl_xor_sync(0xffffffffu, per0, o);
            pel1 += __shfl_xor_sync(0xffffffffu, pel1, o);
            per1 += __shfl_xor_sync(0xffffffffu, per1, o);
        }
        if (q == 0) {
            if (r0 < NNODES) { g_el1[r0 * 4 + h] = pel0; g_er1[r0 * 4 + h] = per0; }
            if (r1 < NNODES) { g_el1[r1 * 4 + h] = pel1; g_er1[r1 * 4 + h] = per1; }
        }
    }
    // store h1 as fp16
#pragma unroll
    for (int nt = 0; nt < 16; ++nt) {
        int c0 = nt * 8 + q * 2;
        if (r0 < NNODES)
            ((__half2*)g_h1)[(size_t)r0 * 64 + (c0 >> 1)] =
                __floats2half2_rn(d[nt][0], d[nt][1]);
        if (r1 < NNODES)
            ((__half2*)g_h1)[(size_t)r1 * 64 + (c0 >> 1)] =
                __floats2half2_rn(d[nt][2], d[nt][3]);
    }
}

// ---------------- GEMM2: h2 = x2 @ W2 (fp16 out), fused el2/er2 (fp32) ------
__global__ __launch_bounds__(128) void gemm2_kernel(
    const float* __restrict__ W, const float* __restrict__ al,
    const float* __restrict__ ar) {
    __shared__ float4 sX[64 * 32];  // 32 KB
    int tid = threadIdx.x;
    int nb = blockIdx.x * 64;
    for (int i = tid; i < 64 * 32; i += 128) {
        int nn = nb + (i >> 5);
        sX[i] = (nn < NNODES) ? ((const float4*)g_x2)[(size_t)nn * 32 + (i & 31)]
                              : make_float4(0.f, 0.f, 0.f, 0.f);
    }
    __syncthreads();
    int l = tid & 31, w = tid >> 5;
    int o = l & 7, g = l >> 3;
    float4 alv = ((const float4*)al)[o];
    float4 arv = ((const float4*)ar)[o];
    float4 acc[4];
#pragma unroll
    for (int i = 0; i < 4; i++) acc[i] = make_float4(0.f, 0.f, 0.f, 0.f);
    const float4* xw = sX + (w * 16 + g * 4) * 32;
    const float4* W4 = (const float4*)W;
#pragma unroll 8
    for (int k4 = 0; k4 < 32; ++k4) {
        float4 w0 = __ldg(&W4[(4 * k4 + 0) * 8 + o]);
        float4 w1 = __ldg(&W4[(4 * k4 + 1) * 8 + o]);
        float4 w2 = __ldg(&W4[(4 * k4 + 2) * 8 + o]);
        float4 w3 = __ldg(&W4[(4 * k4 + 3) * 8 + o]);
#pragma unroll
        for (int i = 0; i < 4; i++) {
            float4 xv = xw[i * 32 + k4];
            fma4(acc[i], xv.x, w0);
            fma4(acc[i], xv.y, w1);
            fma4(acc[i], xv.z, w2);
            fma4(acc[i], xv.w, w3);
        }
    }
#pragma unroll
    for (int i = 0; i < 4; i++) {
        int n = nb + w * 16 + g * 4 + i;
        float4 a = acc[i];
        float pel = dot4(a, alv);
        float per = dot4(a, arv);
#pragma unroll
        for (int d = 4; d >= 1; d >>= 1) {
            pel += __shfl_down_sync(0xffffffffu, pel, d);
            per += __shfl_down_sync(0xffffffffu, per, d);
        }
        if (n < NNODES) {
            ((uint2*)g_h2)[(size_t)n * 8 + o] = pack_half4(a);
            if (o == 0) { g_el2[n] = pel; g_er2[n] = per; }
        }
    }
}

// ---------------- CSR build -------------------------------------------------
__global__ void zero_deg_kernel() {
    int i = blockIdx.x * blockDim.x + threadIdx.x;
    if (i < NNODES) g_deg[i] = 0;
}
__global__ void count_kernel(const int* __restrict__ dst) {
    int i = blockIdx.x * blockDim.x + threadIdx.x;
    if (i < NEDGES) atomicAdd(&g_deg[dst[i]], 1);
}
__global__ void scan1_kernel() {
    __shared__ int s[1024];
    int i = blockIdx.x * 1024 + threadIdx.x;
    int v = (i < NNODES) ? g_deg[i] : 0;
    s[threadIdx.x] = v;
    __syncthreads();
    for (int off = 1; off < 1024; off <<= 1) {
        int t = (threadIdx.x >= off) ? s[threadIdx.x - off] : 0;
        __syncthreads();
        s[threadIdx.x] += t;
        __syncthreads();
    }
    if (i < NNODES) g_rowptr[i + 1] = s[threadIdx.x];
    if (threadIdx.x == 1023) g_bsums[blockIdx.x] = s[1023];
}
__global__ void scan2_kernel(int nblk) {
    __shared__ int s[128];
    int v = (threadIdx.x < nblk) ? g_bsums[threadIdx.x] : 0;
    s[threadIdx.x] = v;
    __syncthreads();
    for (int off = 1; off < 128; off <<= 1) {
        int t = (threadIdx.x >= off) ? s[threadIdx.x - off] : 0;
        __syncthreads();
        s[threadIdx.x] += t;
        __syncthreads();
    }
    g_boff[threadIdx.x] = s[threadIdx.x] - v;  // exclusive prefix of block sums
}
__global__ void scan3_kernel() {  // finalize rowptr AND init cursor
    int i = blockIdx.x * 1024 + threadIdx.x;
    if (i < NNODES) {
        int v = g_rowptr[i + 1] + g_boff[blockIdx.x];
        g_rowptr[i + 1] = v;
        if (i + 1 < NNODES) g_cursor[i + 1] = v;
    }
    if (i == 0) { g_rowptr[0] = 0; g_cursor[0] = 0; }
}
__global__ void fill_kernel(const int* __restrict__ src, const int* __restrict__ dst) {
    int i = blockIdx.x * blockDim.x + threadIdx.x;
    if (i < NEDGES) {
        int d = dst[i];
        int p = atomicAdd(&g_cursor[d], 1);
        g_csrc[p] = src[i];
    }
}

// ---------------- AGG layer1: warp per dst node, 1-pass, pipelined ----------
__global__ __launch_bounds__(256) void agg1_kernel(const float* __restrict__ b1) {
    int n = (blockIdx.x * 256 + threadIdx.x) >> 5;
    if (n >= NNODES) return;
    int l = threadIdx.x & 31;
    int h = l >> 3;
    int s0 = g_rowptr[n], s1 = g_rowptr[n + 1];
    float4 bv = ((const float4*)b1)[l];
    float4 res = bv;
    if (s1 > s0) {
        float ern = g_er1[n * 4 + h];
        float sm = 0.f;
        float4 acc = make_float4(0.f, 0.f, 0.f, 0.f);
        int s = g_csrc[s0];
        float els = __ldg(&g_el1[s * 4 + h]);
        for (int j = s0; j < s1; ++j) {
            int snext = (j + 1 < s1) ? g_csrc[j + 1] : 0;
            float elnext = __ldg(&g_el1[snext * 4 + h]);
            float e = els + ern;
            e = (e > 0.f) ? e : NEG * e;
            float wg = __expf(fminf(e, 60.f));
            uint2 p = ((const uint2*)g_h1)[(size_t)s * 32 + l];
            float2 f01 = __half22float2(*(__half2*)&p.x);
            float2 f23 = __half22float2(*(__half2*)&p.y);
            sm += wg;
            acc.x = fmaf(wg, f01.x, acc.x);
            acc.y = fmaf(wg, f01.y, acc.y);
            acc.z = fmaf(wg, f23.x, acc.z);
            acc.w = fmaf(wg, f23.y, acc.w);
            s = snext;
            els = elnext;
        }
        float inv = 1.f / sm;
        res = make_float4(fmaf(acc.x, inv, bv.x), fmaf(acc.y, inv, bv.y),
                          fmaf(acc.z, inv, bv.z), fmaf(acc.w, inv, bv.w));
    }
    res.x = res.x > 0.f ? res.x : expm1f(res.x);
    res.y = res.y > 0.f ? res.y : expm1f(res.y);
    res.z = res.z > 0.f ? res.z : expm1f(res.z);
    res.w = res.w > 0.f ? res.w : expm1f(res.w);
    ((float4*)g_x2)[(size_t)n * 32 + l] = res;
}

// ---------------- AGG layer2: warp per dst node, 1-pass, pipelined ----------
__global__ __launch_bounds__(256) void agg2_kernel(const float* __restrict__ b2,
                                                   float* __restrict__ out) {
    int n = (blockIdx.x * 256 + threadIdx.x) >> 5;
    if (n >= NNODES) return;
    int l = threadIdx.x & 31;
    int s0 = g_rowptr[n], s1 = g_rowptr[n + 1];
    float bv = b2[l];
    float val = bv;
    if (s1 > s0) {
        float ern = g_er2[n];
        float sm = 0.f, acc = 0.f;
        int s = g_csrc[s0];
        float els = __ldg(&g_el2[s]);
        for (int j = s0; j < s1; ++j) {
            int snext = (j + 1 < s1) ? g_csrc[j + 1] : 0;
            float elnext = __ldg(&g_el2[snext]);
            float e = els + ern;
            e = (e > 0.f) ? e : NEG * e;
            float wg = __expf(fminf(e, 60.f));
            float f = __half2float(g_h2[(size_t)s * 32 + l]);
            sm += wg;
            acc = fmaf(wg, f, acc);
            s = snext;
            els = elnext;
        }
        val = acc / sm + bv;
    }
    out[(size_t)n * 32 + l] = val;
}

// ---------------- launch ----------------------------------------------------
extern "C" void kernel_launch(void* const* d_in, const int* in_sizes, int n_in,
                              void* d_out, int out_size) {
    const float* x   = (const float*)d_in[0];
    const int*   src = (const int*)d_in[1];
    const int*   dst = (const int*)d_in[2];
    const float* W1  = (const float*)d_in[3];
    const float* al1 = (const float*)d_in[4];
    const float* ar1 = (const float*)d_in[5];
    const float* b1  = (const float*)d_in[6];
    const float* W2  = (const float*)d_in[7];
    const float* al2 = (const float*)d_in[8];
    const float* ar2 = (const float*)d_in[9];
    const float* b2  = (const float*)d_in[10];
    float* out = (float*)d_out;

    const int nscan = (NNODES + 1023) / 1024;

    cudaFuncSetAttribute(gemm1_kernel,
                         cudaFuncAttributeMaxDynamicSharedMemorySize, GEMM1_SMEM);

    // launch order puts gemm1 at index 3 (the slot ncu captures)
    zero_deg_kernel<<<(NNODES + 255) / 256, 256>>>();
    count_kernel<<<(NEDGES + 255) / 256, 256>>>(dst);
    scan1_kernel<<<nscan, 1024>>>();
    gemm1_kernel<<<(NNODES + GM_ROWS - 1) / GM_ROWS, 128, GEMM1_SMEM>>>(x, W1, al1, ar1);
    scan2_kernel<<<1, 128>>>(nscan);
    scan3_kernel<<<nscan, 1024>>>();
    fill_kernel<<<(NEDGES + 255) / 256, 256>>>(src, dst);

    agg1_kernel<<<(NNODES * 32 + 255) / 256, 256>>>(b1);
    gemm2_kernel<<<(NNODES + 63) / 64, 128>>>(W2, al2, ar2);
    agg2_kernel<<<(NNODES * 32 + 255) / 256, 256>>>(b2, out);
}

// round 5
// speedup vs baseline: 1.2889x; 1.0587x over previous
#include <cuda_runtime.h>
#include <cuda_fp16.h>
#include <math.h>

#define NNODES 100000
#define NEDGES 1600000
#define NEG 0.2f

// ---------------- scratch (device globals; no allocation allowed) ----------
__device__ __half g_w1h[128 * 128];     // W1 fp16, transposed: [n][k]
__device__ __half g_h1[NNODES * 128];   // layer1 projected features, fp16
__device__ float  g_el1[NNODES * 4];
__device__ float  g_er1[NNODES * 4];
__device__ float  g_x2[NNODES * 128];   // layer1 output after elu (fp32)
__device__ __half g_h2[NNODES * 32];    // layer2 projected features, fp16
__device__ float  g_el2[NNODES];
__device__ float  g_er2[NNODES];
__device__ int    g_deg[NNODES];
__device__ int    g_rowptr[NNODES + 1];
__device__ int    g_cursor[NNODES];
__device__ int    g_csrc[NEDGES];
__device__ int    g_bsums[128];
__device__ int    g_boff[128];

__device__ __forceinline__ void fma4(float4& a, float s, float4 b) {
    a.x = fmaf(s, b.x, a.x);
    a.y = fmaf(s, b.y, a.y);
    a.z = fmaf(s, b.z, a.z);
    a.w = fmaf(s, b.w, a.w);
}
__device__ __forceinline__ float dot4(float4 a, float4 b) {
    return a.x * b.x + a.y * b.y + a.z * b.z + a.w * b.w;
}
__device__ __forceinline__ uint2 pack_half4(float4 a) {
    __half2 p0 = __floats2half2_rn(a.x, a.y);
    __half2 p1 = __floats2half2_rn(a.z, a.w);
    uint2 u;
    u.x = *(unsigned*)&p0;
    u.y = *(unsigned*)&p1;
    return u;
}

// ---------------- small setup kernels ---------------------------------------
__global__ __launch_bounds__(256) void convw1_kernel(const float* __restrict__ W) {
    for (int i = threadIdx.x + blockIdx.x * 256; i < 128 * 128; i += 256 * 8) {
        int k = i >> 7, n = i & 127;
        g_w1h[n * 128 + k] = __float2half_rn(W[i]);
    }
}
__global__ void zero_deg_kernel() {
    int i = blockIdx.x * blockDim.x + threadIdx.x;
    if (i < NNODES) g_deg[i] = 0;
}

// ---------------- GEMM1 via HMMA: h1 = x @ W1 (fp16 out), fused el/er -------
// 256 threads (8 warps), 128 nodes/block; warp w -> rows w*16..w*16+15.
#define GM_ROWS 128
#define XS_STRIDE 136   // halves; 272 B rows (16B-aligned) -> conflict-free
#define WS_STRIDE 136
#define GEMM1_SMEM ((GM_ROWS * XS_STRIDE + 128 * WS_STRIDE) * 2)

__global__ __launch_bounds__(256) void gemm1_kernel(
    const float* __restrict__ x, const float* __restrict__ al,
    const float* __restrict__ ar) {
    extern __shared__ __half smem_dyn[];
    __half* xs = smem_dyn;                        // [128][136]
    __half* ws = smem_dyn + GM_ROWS * XS_STRIDE;  // [128][136]  ws[n][k]
    int tid = threadIdx.x;
    int nb = blockIdx.x * GM_ROWS;

    // copy W1 (fp16, pre-transposed) via uint4: 2048 x 16B
    for (int i = tid; i < 2048; i += 256) {
        int row = i >> 4, c = i & 15;
        *(uint4*)(ws + row * WS_STRIDE + c * 8) =
            *(const uint4*)(g_w1h + row * 128 + c * 8);
    }
    // load + convert x tile: 128 rows x 32 float4
    for (int i = tid; i < GM_ROWS * 32; i += 256) {
        int r = i >> 5, c4 = i & 31;
        int nn = nb + r;
        float4 v = (nn < NNODES) ? ((const float4*)x)[(size_t)nn * 32 + c4]
                                 : make_float4(0.f, 0.f, 0.f, 0.f);
        __half2 h0 = __floats2half2_rn(v.x, v.y);
        __half2 h1 = __floats2half2_rn(v.z, v.w);
        uint2 u;
        u.x = *(unsigned*)&h0;
        u.y = *(unsigned*)&h1;
        *(uint2*)(xs + r * XS_STRIDE + c4 * 4) = u;
    }
    __syncthreads();

    int l = tid & 31, w = tid >> 5;
    int g4 = l >> 2, q = l & 3;
    float d[16][4];
#pragma unroll
    for (int nt = 0; nt < 16; ++nt)
#pragma unroll
        for (int c = 0; c < 4; ++c) d[nt][c] = 0.f;

    const __half* xw = xs + (w * 16) * XS_STRIDE;
#pragma unroll
    for (int ks = 0; ks < 8; ++ks) {
        int kb = ks * 16 + q * 2;
        unsigned a0 = *(const unsigned*)(xw + (g4    ) * XS_STRIDE + kb    );
        unsigned a1 = *(const unsigned*)(xw + (g4 + 8) * XS_STRIDE + kb    );
        unsigned a2 = *(const unsigned*)(xw + (g4    ) * XS_STRIDE + kb + 8);
        unsigned a3 = *(const unsigned*)(xw + (g4 + 8) * XS_STRIDE + kb + 8);
#pragma unroll
        for (int nt = 0; nt < 16; ++nt) {
            const __half* wb = ws + (nt * 8 + g4) * WS_STRIDE + kb;
            unsigned b0 = *(const unsigned*)(wb);
            unsigned b1 = *(const unsigned*)(wb + 8);
            asm volatile(
                "mma.sync.aligned.m16n8k16.row.col.f32.f16.f16.f32 "
                "{%0,%1,%2,%3}, {%4,%5,%6,%7}, {%8,%9}, {%0,%1,%2,%3};"
                : "+f"(d[nt][0]), "+f"(d[nt][1]), "+f"(d[nt][2]), "+f"(d[nt][3])
                : "r"(a0), "r"(a1), "r"(a2), "r"(a3), "r"(b0), "r"(b1));
        }
    }

    int r0 = nb + w * 16 + g4;
    int r1 = r0 + 8;
#pragma unroll
    for (int h = 0; h < 4; ++h) {
        float pel0 = 0.f, per0 = 0.f, pel1 = 0.f, per1 = 0.f;
#pragma unroll
        for (int t = 0; t < 4; ++t) {
            int nt = h * 4 + t;
            int c0 = nt * 8 + q * 2;
            float alv0 = __ldg(&al[c0]), alv1 = __ldg(&al[c0 + 1]);
            float arv0 = __ldg(&ar[c0]), arv1 = __ldg(&ar[c0 + 1]);
            pel0 += d[nt][0] * alv0 + d[nt][1] * alv1;
            per0 += d[nt][0] * arv0 + d[nt][1] * arv1;
            pel1 += d[nt][2] * alv0 + d[nt][3] * alv1;
            per1 += d[nt][2] * arv0 + d[nt][3] * arv1;
        }
#pragma unroll
        for (int o = 1; o < 4; o <<= 1) {
            pel0 += __shfl_xor_sync(0xffffffffu, pel0, o);
            per0 += __shfl_xor_sync(0xffffffffu, per0, o);
            pel1 += __shfl_xor_sync(0xffffffffu, pel1, o);
            per1 += __shfl_xor_sync(0xffffffffu, per1, o);
        }
        if (q == 0) {
            if (r0 < NNODES) { g_el1[r0 * 4 + h] = pel0; g_er1[r0 * 4 + h] = per0; }
            if (r1 < NNODES) { g_el1[r1 * 4 + h] = pel1; g_er1[r1 * 4 + h] = per1; }
        }
    }
#pragma unroll
    for (int nt = 0; nt < 16; ++nt) {
        int c0 = nt * 8 + q * 2;
        if (r0 < NNODES)
            ((__half2*)g_h1)[(size_t)r0 * 64 + (c0 >> 1)] =
                __floats2half2_rn(d[nt][0], d[nt][1]);
        if (r1 < NNODES)
            ((__half2*)g_h1)[(size_t)r1 * 64 + (c0 >> 1)] =
                __floats2half2_rn(d[nt][2], d[nt][3]);
    }
}

// ---------------- GEMM2: h2 = x2 @ W2 (fp16 out), fused el2/er2 (fp32) ------
__global__ __launch_bounds__(128) void gemm2_kernel(
    const float* __restrict__ W, const float* __restrict__ al,
    const float* __restrict__ ar) {
    __shared__ float4 sX[64 * 32];  // 32 KB
    int tid = threadIdx.x;
    int nb = blockIdx.x * 64;
    for (int i = tid; i < 64 * 32; i += 128) {
        int nn = nb + (i >> 5);
        sX[i] = (nn < NNODES) ? ((const float4*)g_x2)[(size_t)nn * 32 + (i & 31)]
                              : make_float4(0.f, 0.f, 0.f, 0.f);
    }
    __syncthreads();
    int l = tid & 31, w = tid >> 5;
    int o = l & 7, g = l >> 3;
    float4 alv = ((const float4*)al)[o];
    float4 arv = ((const float4*)ar)[o];
    float4 acc[4];
#pragma unroll
    for (int i = 0; i < 4; i++) acc[i] = make_float4(0.f, 0.f, 0.f, 0.f);
    const float4* xw = sX + (w * 16 + g * 4) * 32;
    const float4* W4 = (const float4*)W;
#pragma unroll 8
    for (int k4 = 0; k4 < 32; ++k4) {
        float4 w0 = __ldg(&W4[(4 * k4 + 0) * 8 + o]);
        float4 w1 = __ldg(&W4[(4 * k4 + 1) * 8 + o]);
        float4 w2 = __ldg(&W4[(4 * k4 + 2) * 8 + o]);
        float4 w3 = __ldg(&W4[(4 * k4 + 3) * 8 + o]);
#pragma unroll
        for (int i = 0; i < 4; i++) {
            float4 xv = xw[i * 32 + k4];
            fma4(acc[i], xv.x, w0);
            fma4(acc[i], xv.y, w1);
            fma4(acc[i], xv.z, w2);
            fma4(acc[i], xv.w, w3);
        }
    }
#pragma unroll
    for (int i = 0; i < 4; i++) {
        int n = nb + w * 16 + g * 4 + i;
        float4 a = acc[i];
        float pel = dot4(a, alv);
        float per = dot4(a, arv);
#pragma unroll
        for (int d = 4; d >= 1; d >>= 1) {
            pel += __shfl_down_sync(0xffffffffu, pel, d);
            per += __shfl_down_sync(0xffffffffu, per, d);
        }
        if (n < NNODES) {
            ((uint2*)g_h2)[(size_t)n * 8 + o] = pack_half4(a);
            if (o == 0) { g_el2[n] = pel; g_er2[n] = per; }
        }
    }
}

// ---------------- CSR build -------------------------------------------------
__global__ void count_kernel(const int* __restrict__ dst) {
    int i = blockIdx.x * blockDim.x + threadIdx.x;
    int base = i * 4;
    if (base + 3 < NEDGES) {
        int4 d = ((const int4*)dst)[i];
        atomicAdd(&g_deg[d.x], 1);
        atomicAdd(&g_deg[d.y], 1);
        atomicAdd(&g_deg[d.z], 1);
        atomicAdd(&g_deg[d.w], 1);
    } else {
        for (int j = base; j < NEDGES; ++j) atomicAdd(&g_deg[dst[j]], 1);
    }
}
__global__ void scan1_kernel() {
    __shared__ int s[1024];
    int i = blockIdx.x * 1024 + threadIdx.x;
    int v = (i < NNODES) ? g_deg[i] : 0;
    s[threadIdx.x] = v;
    __syncthreads();
    for (int off = 1; off < 1024; off <<= 1) {
        int t = (threadIdx.x >= off) ? s[threadIdx.x - off] : 0;
        __syncthreads();
        s[threadIdx.x] += t;
        __syncthreads();
    }
    if (i < NNODES) g_rowptr[i + 1] = s[threadIdx.x];
    if (threadIdx.x == 1023) g_bsums[blockIdx.x] = s[1023];
}
__global__ void scan2_kernel(int nblk) {
    __shared__ int s[128];
    int v = (threadIdx.x < nblk) ? g_bsums[threadIdx.x] : 0;
    s[threadIdx.x] = v;
    __syncthreads();
    for (int off = 1; off < 128; off <<= 1) {
        int t = (threadIdx.x >= off) ? s[threadIdx.x - off] : 0;
        __syncthreads();
        s[threadIdx.x] += t;
        __syncthreads();
    }
    g_boff[threadIdx.x] = s[threadIdx.x] - v;
}
__global__ void scan3_kernel() {  // finalize rowptr AND init cursor
    int i = blockIdx.x * 1024 + threadIdx.x;
    if (i < NNODES) {
        int v = g_rowptr[i + 1] + g_boff[blockIdx.x];
        g_rowptr[i + 1] = v;
        if (i + 1 < NNODES) g_cursor[i + 1] = v;
    }
    if (i == 0) { g_rowptr[0] = 0; g_cursor[0] = 0; }
}
__global__ void fill_kernel(const int* __restrict__ src, const int* __restrict__ dst) {
    int i = blockIdx.x * blockDim.x + threadIdx.x;
    int base = i * 4;
    if (base + 3 < NEDGES) {
        int4 d = ((const int4*)dst)[i];
        int4 s = ((const int4*)src)[i];
        g_csrc[atomicAdd(&g_cursor[d.x], 1)] = s.x;
        g_csrc[atomicAdd(&g_cursor[d.y], 1)] = s.y;
        g_csrc[atomicAdd(&g_cursor[d.z], 1)] = s.z;
        g_csrc[atomicAdd(&g_cursor[d.w], 1)] = s.w;
    } else {
        for (int j = base; j < NEDGES; ++j)
            g_csrc[atomicAdd(&g_cursor[dst[j]], 1)] = src[j];
    }
}

// ---------------- AGG layer1: warp per dst node, 1-pass, pipelined ----------
__global__ __launch_bounds__(256) void agg1_kernel(const float* __restrict__ b1) {
    int n = (blockIdx.x * 256 + threadIdx.x) >> 5;
    if (n >= NNODES) return;
    int l = threadIdx.x & 31;
    int h = l >> 3;
    int s0 = g_rowptr[n], s1 = g_rowptr[n + 1];
    float4 bv = ((const float4*)b1)[l];
    float4 res = bv;
    if (s1 > s0) {
        float ern = g_er1[n * 4 + h];
        float sm = 0.f;
        float4 acc = make_float4(0.f, 0.f, 0.f, 0.f);
        int s = g_csrc[s0];
        float els = __ldg(&g_el1[s * 4 + h]);
        for (int j = s0; j < s1; ++j) {
            int snext = (j + 1 < s1) ? g_csrc[j + 1] : 0;
            float elnext = __ldg(&g_el1[snext * 4 + h]);
            float e = els + ern;
            e = (e > 0.f) ? e : NEG * e;
            float wg = __expf(fminf(e, 60.f));
            uint2 p = ((const uint2*)g_h1)[(size_t)s * 32 + l];
            float2 f01 = __half22float2(*(__half2*)&p.x);
            float2 f23 = __half22float2(*(__half2*)&p.y);
            sm += wg;
            acc.x = fmaf(wg, f01.x, acc.x);
            acc.y = fmaf(wg, f01.y, acc.y);
            acc.z = fmaf(wg, f23.x, acc.z);
            acc.w = fmaf(wg, f23.y, acc.w);
            s = snext;
            els = elnext;
        }
        float inv = 1.f / sm;
        res = make_float4(fmaf(acc.x, inv, bv.x), fmaf(acc.y, inv, bv.y),
                          fmaf(acc.z, inv, bv.z), fmaf(acc.w, inv, bv.w));
    }
    res.x = res.x > 0.f ? res.x : expm1f(res.x);
    res.y = res.y > 0.f ? res.y : expm1f(res.y);
    res.z = res.z > 0.f ? res.z : expm1f(res.z);
    res.w = res.w > 0.f ? res.w : expm1f(res.w);
    ((float4*)g_x2)[(size_t)n * 32 + l] = res;
}

// ---------------- AGG layer2: warp per dst node, 1-pass, pipelined ----------
__global__ __launch_bounds__(256) void agg2_kernel(const float* __restrict__ b2,
                                                   float* __restrict__ out) {
    int n = (blockIdx.x * 256 + threadIdx.x) >> 5;
    if (n >= NNODES) return;
    int l = threadIdx.x & 31;
    int s0 = g_rowptr[n], s1 = g_rowptr[n + 1];
    float bv = b2[l];
    float val = bv;
    if (s1 > s0) {
        float ern = g_er2[n];
        float sm = 0.f, acc = 0.f;
        int s = g_csrc[s0];
        float els = __ldg(&g_el2[s]);
        for (int j = s0; j < s1; ++j) {
            int snext = (j + 1 < s1) ? g_csrc[j + 1] : 0;
            float elnext = __ldg(&g_el2[snext]);
            float e = els + ern;
            e = (e > 0.f) ? e : NEG * e;
            float wg = __expf(fminf(e, 60.f));
            float f = __half2float(g_h2[(size_t)s * 32 + l]);
            sm += wg;
            acc = fmaf(wg, f, acc);
            s = snext;
            els = elnext;
        }
        val = acc / sm + bv;
    }
    out[(size_t)n * 32 + l] = val;
}

// ---------------- launch ----------------------------------------------------
extern "C" void kernel_launch(void* const* d_in, const int* in_sizes, int n_in,
                              void* d_out, int out_size) {
    const float* x   = (const float*)d_in[0];
    const int*   src = (const int*)d_in[1];
    const int*   dst = (const int*)d_in[2];
    const float* W1  = (const float*)d_in[3];
    const float* al1 = (const float*)d_in[4];
    const float* ar1 = (const float*)d_in[5];
    const float* b1  = (const float*)d_in[6];
    const float* W2  = (const float*)d_in[7];
    const float* al2 = (const float*)d_in[8];
    const float* ar2 = (const float*)d_in[9];
    const float* b2  = (const float*)d_in[10];
    float* out = (float*)d_out;

    const int nscan = (NNODES + 1023) / 1024;

    cudaFuncSetAttribute(gemm1_kernel,
                         cudaFuncAttributeMaxDynamicSharedMemorySize, GEMM1_SMEM);

    zero_deg_kernel<<<(NNODES + 255) / 256, 256>>>();
    convw1_kernel<<<8, 256>>>(W1);
    count_kernel<<<(NEDGES / 4 + 255) / 256, 256>>>(dst);
    // gemm1 at launch index 3 (the slot ncu captures)
    gemm1_kernel<<<(NNODES + GM_ROWS - 1) / GM_ROWS, 256, GEMM1_SMEM>>>(x, al1, ar1);
    scan1_kernel<<<nscan, 1024>>>();
    scan2_kernel<<<1, 128>>>(nscan);
    scan3_kernel<<<nscan, 1024>>>();
    fill_kernel<<<(NEDGES / 4 + 255) / 256, 256>>>(src, dst);

    agg1_kernel<<<(NNODES * 32 + 255) / 256, 256>>>(b1);
    gemm2_kernel<<<(NNODES + 63) / 64, 128>>>(W2, al2, ar2);
    agg2_kernel<<<(NNODES * 32 + 255) / 256, 256>>>(b2, out);
}